// round 6
// baseline (speedup 1.0000x reference)
#include <cuda_runtime.h>
#include <cuda_bf16.h>

#define DIMC 1024
#define NHEAD 16
#define HDIM 64
#define BB 4
#define TT 2048
#define MROWS (BB * TT)   // 8192

// Scratch (device globals — allocation-free contract)
__device__ float g_q[BB * NHEAD * TT * HDIM];   // [B,H,T,D]
__device__ float g_k[BB * NHEAD * TT * HDIM];
__device__ float g_v[BB * NHEAD * TT * HDIM];
__device__ float g_att[MROWS * DIMC];           // [B*T, C] attention output

__device__ __forceinline__ unsigned f2tf32(float x) {
    unsigned u;
    asm("cvt.rna.tf32.f32 %0, %1;" : "=r"(u) : "f"(x));
    return u;
}

// 2^x on the FMA/ALU pipes (no MUFU). x <= 0 expected; clamped at -120.
__device__ __forceinline__ float exp2_fast(float x) {
    x = fmaxf(x, -120.f);
    float n = floorf(x);
    float f = x - n;                 // [0,1)
    float p = 1.78656e-4f;           // ~(ln2)^6/720
    p = fmaf(p, f, 1.33336e-3f);
    p = fmaf(p, f, 9.61813e-3f);
    p = fmaf(p, f, 5.55041e-2f);
    p = fmaf(p, f, 2.40226507e-1f);
    p = fmaf(p, f, 6.93147181e-1f);
    p = fmaf(p, f, 1.0f);
    return __uint_as_float(__float_as_uint(p) + (((int)n) << 23));
}

#define MMA_TF32(d, a, b)                                                    \
    asm volatile("mma.sync.aligned.m16n8k8.row.col.f32.tf32.tf32.f32 "        \
                 "{%0,%1,%2,%3}, {%4,%5,%6,%7}, {%8,%9}, {%0,%1,%2,%3};"      \
                 : "+f"(d[0]), "+f"(d[1]), "+f"(d[2]), "+f"(d[3])             \
                 : "r"(a[0]), "r"(a[1]), "r"(a[2]), "r"(a[3]),                \
                   "r"(b[0]), "r"(b[1]))

// ---------------------------------------------------------------------------
// TF32 tensor-core GEMM: C[M,N] = A[M,K] @ W[N,K]^T.
// 128x128 block tile, BK=8, 128 threads = 4 warps in a 2x2 grid, each warp
// owns a 64x64 tile (halves fragment-LDS traffic per MMA vs 64x32).
// Double-buffered tf32 smem staging. qkv_mode scatters to [B,H,T,D].
// ---------------------------------------------------------------------------
#define KSTRIDE 136

__global__ __launch_bounds__(128, 2) void gemm_kernel(
    const float* __restrict__ A,
    const float* __restrict__ W0, const float* __restrict__ W1,
    const float* __restrict__ W2,
    float* __restrict__ D0, float* __restrict__ D1, float* __restrict__ D2,
    int qkv_mode)
{
    __shared__ unsigned As[2][8][KSTRIDE];
    __shared__ unsigned Bs[2][8][KSTRIDE];

    const float* W = W0;
    float* D = D0;
    if (blockIdx.z == 1) { W = W1; D = D1; }
    else if (blockIdx.z == 2) { W = W2; D = D2; }

    const int tid  = threadIdx.x;
    const int lane = tid & 31;
    const int w    = tid >> 5;
    const int wm   = w >> 1;          // 0..1 : rows wm*64..+63
    const int wn   = w & 1;           // 0..1 : cols wn*64..+63
    const int r0 = blockIdx.y * 128;
    const int c0 = blockIdx.x * 128;

    const int fr = lane >> 2;            // 0..7
    const int fc = lane & 3;             // 0..3

    // staging: each of 128 threads owns one row, loads 8 contiguous k floats
    const float* Ap = A + (size_t)(r0 + tid) * DIMC;
    const float* Wp = W + (size_t)(c0 + tid) * DIMC;

    float acc[4][8][4];
#pragma unroll
    for (int mi = 0; mi < 4; mi++)
#pragma unroll
        for (int ni = 0; ni < 8; ni++)
#pragma unroll
            for (int e = 0; e < 4; e++) acc[mi][ni][e] = 0.f;

    // prologue: stage tile 0 (tf32-rounded)
    {
        float4 a0 = *(const float4*)(Ap);
        float4 a1 = *(const float4*)(Ap + 4);
        float4 b0 = *(const float4*)(Wp);
        float4 b1 = *(const float4*)(Wp + 4);
        As[0][0][tid] = f2tf32(a0.x); As[0][1][tid] = f2tf32(a0.y);
        As[0][2][tid] = f2tf32(a0.z); As[0][3][tid] = f2tf32(a0.w);
        As[0][4][tid] = f2tf32(a1.x); As[0][5][tid] = f2tf32(a1.y);
        As[0][6][tid] = f2tf32(a1.z); As[0][7][tid] = f2tf32(a1.w);
        Bs[0][0][tid] = f2tf32(b0.x); Bs[0][1][tid] = f2tf32(b0.y);
        Bs[0][2][tid] = f2tf32(b0.z); Bs[0][3][tid] = f2tf32(b0.w);
        Bs[0][4][tid] = f2tf32(b1.x); Bs[0][5][tid] = f2tf32(b1.y);
        Bs[0][6][tid] = f2tf32(b1.z); Bs[0][7][tid] = f2tf32(b1.w);
    }
    __syncthreads();

    int buf = 0;
    for (int kt = 1; kt <= DIMC / 8; kt++) {
        float4 na0, na1, nb0, nb1;
        const bool more = (kt < DIMC / 8);
        if (more) {
            na0 = *(const float4*)(Ap + kt * 8);
            na1 = *(const float4*)(Ap + kt * 8 + 4);
            nb0 = *(const float4*)(Wp + kt * 8);
            nb1 = *(const float4*)(Wp + kt * 8 + 4);
        }

        // fragments: warp tile 64x64 -> 4 m-atoms, 8 n-atoms
        unsigned af[4][4], bfr[8][2];
#pragma unroll
        for (int mi = 0; mi < 4; mi++) {
            int r = wm * 64 + mi * 16 + fr;
            af[mi][0] = As[buf][fc][r];
            af[mi][1] = As[buf][fc][r + 8];
            af[mi][2] = As[buf][fc + 4][r];
            af[mi][3] = As[buf][fc + 4][r + 8];
        }
#pragma unroll
        for (int ni = 0; ni < 8; ni++) {
            int n = wn * 64 + ni * 8 + fr;
            bfr[ni][0] = Bs[buf][fc][n];
            bfr[ni][1] = Bs[buf][fc + 4][n];
        }
#pragma unroll
        for (int mi = 0; mi < 4; mi++)
#pragma unroll
            for (int ni = 0; ni < 8; ni++)
                MMA_TF32(acc[mi][ni], af[mi], bfr[ni]);

        if (more) {
            int nb_ = buf ^ 1;
            As[nb_][0][tid] = f2tf32(na0.x); As[nb_][1][tid] = f2tf32(na0.y);
            As[nb_][2][tid] = f2tf32(na0.z); As[nb_][3][tid] = f2tf32(na0.w);
            As[nb_][4][tid] = f2tf32(na1.x); As[nb_][5][tid] = f2tf32(na1.y);
            As[nb_][6][tid] = f2tf32(na1.z); As[nb_][7][tid] = f2tf32(na1.w);
            Bs[nb_][0][tid] = f2tf32(nb0.x); Bs[nb_][1][tid] = f2tf32(nb0.y);
            Bs[nb_][2][tid] = f2tf32(nb0.z); Bs[nb_][3][tid] = f2tf32(nb0.w);
            Bs[nb_][4][tid] = f2tf32(nb1.x); Bs[nb_][5][tid] = f2tf32(nb1.y);
            Bs[nb_][6][tid] = f2tf32(nb1.z); Bs[nb_][7][tid] = f2tf32(nb1.w);
            __syncthreads();
            buf ^= 1;
        }
    }

    // epilogue
    if (!qkv_mode) {
#pragma unroll
        for (int mi = 0; mi < 4; mi++) {
            int r = r0 + wm * 64 + mi * 16 + fr;
#pragma unroll
            for (int ni = 0; ni < 8; ni++) {
                int c = c0 + wn * 64 + ni * 8 + fc * 2;
                *(float2*)(D + (size_t)r * DIMC + c) =
                    make_float2(acc[mi][ni][0], acc[mi][ni][1]);
                *(float2*)(D + (size_t)(r + 8) * DIMC + c) =
                    make_float2(acc[mi][ni][2], acc[mi][ni][3]);
            }
        }
    } else {
#pragma unroll
        for (int mi = 0; mi < 4; mi++) {
            int row = r0 + wm * 64 + mi * 16 + fr;
#pragma unroll
            for (int half = 0; half < 2; half++) {
                int rr = row + half * 8;
                int b = rr >> 11;
                int t = rr & 2047;
#pragma unroll
                for (int ni = 0; ni < 8; ni++) {
                    int cc = wn * 64 + ni * 8 + fc * 2;       // 0..127
                    int h = blockIdx.x * 2 + (cc >> 6);
                    int d = cc & 63;
                    size_t idx = (((size_t)(b * NHEAD + h) * TT + t) * HDIM) + d;
                    *(float2*)(D + idx) =
                        make_float2(acc[mi][ni][half * 2 + 0],
                                    acc[mi][ni][half * 2 + 1]);
                }
            }
        }
    }
}

// ---------------------------------------------------------------------------
// Flash attention, tensor-core edition. BQ=128, BK=64, 256 threads (8 warps,
// 4(m)x2(n)). S and PV via tf32 m16n8k8; online softmax in log2 domain with
// FMA-pipe exp2; P round-trips through smem as tf32.  (unchanged from R5)
// ---------------------------------------------------------------------------
#define ASTRIDE 68

__global__ __launch_bounds__(256, 1) void attn_kernel()
{
    extern __shared__ unsigned smu[];
    unsigned* Qs = smu;                    // [128][68] tf32, scaled by 0.125*log2e
    unsigned* Ks = Qs + 128 * ASTRIDE;     // [64][68]  tf32, natural [k][d]
    unsigned* Vt = Ks + 64 * ASTRIDE;      // [64][68]  tf32, transposed [d][k]
    unsigned* Ps = Vt + 64 * ASTRIDE;      // [128][68] tf32 probs
    float* red_max = (float*)(Ps + 128 * ASTRIDE);  // [2][128]
    float* red_sum = red_max + 2 * 128;             // [2][128]

    const int tid  = threadIdx.x;
    const int lane = tid & 31;
    const int w    = tid >> 5;
    const int wm   = w >> 1;          // 0..3 : rows wm*32..+31
    const int wn   = w & 1;           // 0..1 : cols wn*32..+31
    const int fr   = lane >> 2;
    const int fc   = lane & 3;

    const int bh = blockIdx.y;
    const int q0 = (gridDim.x - 1 - blockIdx.x) * 128;   // heavy tiles first

    const float* Q = g_q + (size_t)bh * TT * HDIM;
    const float* K = g_k + (size_t)bh * TT * HDIM;
    const float* V = g_v + (size_t)bh * TT * HDIM;

    const float qsc = 0.125f * 1.4426950408889634f;  // scale * log2(e)

    // Stage Q (tf32, scaled): 128 x 64
#pragma unroll
    for (int it = 0; it < 8; it++) {
        int e = tid + it * 256;
        int r = e >> 4, dq = (e & 15) * 4;
        float4 v4 = *(const float4*)(Q + (size_t)(q0 + r) * HDIM + dq);
        unsigned* p = &Qs[r * ASTRIDE + dq];
        p[0] = f2tf32(v4.x * qsc); p[1] = f2tf32(v4.y * qsc);
        p[2] = f2tf32(v4.z * qsc); p[3] = f2tf32(v4.w * qsc);
    }

    float O[2][4][4];
#pragma unroll
    for (int mi = 0; mi < 2; mi++)
#pragma unroll
        for (int ni = 0; ni < 4; ni++)
#pragma unroll
            for (int e = 0; e < 4; e++) O[mi][ni][e] = 0.f;
    float m_i[4], l_i[4];
#pragma unroll
    for (int s = 0; s < 4; s++) { m_i[s] = -1e30f; l_i[s] = 0.f; }

    const int ntiles = (q0 >> 6) + 2;

    for (int kt = 0; kt < ntiles; kt++) {
        const int k0 = kt * 64;
        __syncthreads();   // prev PV done before restaging

        // Stage K: Ks[k][d]
#pragma unroll
        for (int it = 0; it < 4; it++) {
            int e = tid + it * 256;
            int k = e >> 4, dq = (e & 15) * 4;
            float4 kv = *(const float4*)(K + (size_t)(k0 + k) * HDIM + dq);
            unsigned* p = &Ks[k * ASTRIDE + dq];
            p[0] = f2tf32(kv.x); p[1] = f2tf32(kv.y);
            p[2] = f2tf32(kv.z); p[3] = f2tf32(kv.w);
        }
        // Stage V transposed: Vt[d][k]
#pragma unroll
        for (int it = 0; it < 4; it++) {
            int e = tid + it * 256;
            int d = e & 63;
            int kq = (e >> 6) * 4;
            float v0 = V[(size_t)(k0 + kq + 0) * HDIM + d];
            float v1 = V[(size_t)(k0 + kq + 1) * HDIM + d];
            float v2 = V[(size_t)(k0 + kq + 2) * HDIM + d];
            float v3 = V[(size_t)(k0 + kq + 3) * HDIM + d];
            *(uint4*)&Vt[d * ASTRIDE + kq] =
                make_uint4(f2tf32(v0), f2tf32(v1), f2tf32(v2), f2tf32(v3));
        }
        __syncthreads();

        // S = Qs @ Ks^T (tf32 mma): per warp 32 rows x 32 cols
        float sacc[2][4][4];
#pragma unroll
        for (int mi = 0; mi < 2; mi++)
#pragma unroll
            for (int ni = 0; ni < 4; ni++)
#pragma unroll
                for (int e = 0; e < 4; e++) sacc[mi][ni][e] = 0.f;

#pragma unroll
        for (int kk = 0; kk < 8; kk++) {
            unsigned af[2][4];
#pragma unroll
            for (int mi = 0; mi < 2; mi++) {
                const unsigned* b = &Qs[(wm * 32 + mi * 16 + fr) * ASTRIDE + kk * 8 + fc];
                af[mi][0] = b[0];
                af[mi][1] = b[8 * ASTRIDE];
                af[mi][2] = b[4];
                af[mi][3] = b[8 * ASTRIDE + 4];
            }
            unsigned bf[4][2];
#pragma unroll
            for (int ni = 0; ni < 4; ni++) {
                const unsigned* b = &Ks[(wn * 32 + ni * 8 + fr) * ASTRIDE + kk * 8 + fc];
                bf[ni][0] = b[0];
                bf[ni][1] = b[4];
            }
#pragma unroll
            for (int mi = 0; mi < 2; mi++)
#pragma unroll
                for (int ni = 0; ni < 4; ni++)
                    MMA_TF32(sacc[mi][ni], af[mi], bf[ni]);
        }

        // Softmax part 1: mask + row max (log2 domain)
        const bool need_mask = (k0 + 63 > q0);
#pragma unroll
        for (int mi = 0; mi < 2; mi++)
#pragma unroll
        for (int h = 0; h < 2; h++) {
            int r = wm * 32 + mi * 16 + fr + h * 8;
            int rg = q0 + r;
            float rm = -1e30f;
#pragma unroll
            for (int ni = 0; ni < 4; ni++)
#pragma unroll
            for (int e = 0; e < 2; e++) {
                float s = sacc[mi][ni][h * 2 + e];
                if (need_mask && (k0 + wn * 32 + ni * 8 + fc * 2 + e > rg))
                    s = -1e30f;
                sacc[mi][ni][h * 2 + e] = s;
                rm = fmaxf(rm, s);
            }
            rm = fmaxf(rm, __shfl_xor_sync(0xffffffffu, rm, 1));
            rm = fmaxf(rm, __shfl_xor_sync(0xffffffffu, rm, 2));
            if (fc == 0) red_max[wn * 128 + r] = rm;
        }
        __syncthreads();

        // Softmax part 2: m/l/alpha, p = 2^(s - m), write P (tf32), rescale O
        float alpha_s[4];
#pragma unroll
        for (int mi = 0; mi < 2; mi++)
#pragma unroll
        for (int h = 0; h < 2; h++) {
            int slot = mi * 2 + h;
            int r = wm * 32 + mi * 16 + fr + h * 8;
            float tm = fmaxf(red_max[r], red_max[128 + r]);
            float mnew = fmaxf(m_i[slot], tm);
            float al = exp2_fast(m_i[slot] - mnew);
            m_i[slot] = mnew;
            alpha_s[slot] = al;
            float rs = 0.f;
#pragma unroll
            for (int ni = 0; ni < 4; ni++) {
                float p0 = exp2_fast(sacc[mi][ni][h * 2 + 0] - mnew);
                float p1 = exp2_fast(sacc[mi][ni][h * 2 + 1] - mnew);
                rs += p0 + p1;
                *(uint2*)&Ps[r * ASTRIDE + wn * 32 + ni * 8 + fc * 2] =
                    make_uint2(f2tf32(p0), f2tf32(p1));
            }
            rs += __shfl_xor_sync(0xffffffffu, rs, 1);
            rs += __shfl_xor_sync(0xffffffffu, rs, 2);
            if (fc == 0) red_sum[wn * 128 + r] = rs;
#pragma unroll
            for (int ni = 0; ni < 4; ni++) {
                O[mi][ni][h * 2 + 0] *= al;
                O[mi][ni][h * 2 + 1] *= al;
            }
        }
        __syncthreads();

        // l update
#pragma unroll
        for (int mi = 0; mi < 2; mi++)
#pragma unroll
        for (int h = 0; h < 2; h++) {
            int slot = mi * 2 + h;
            int r = wm * 32 + mi * 16 + fr + h * 8;
            l_i[slot] = l_i[slot] * alpha_s[slot] + red_sum[r] + red_sum[128 + r];
        }

        // O += P @ V (tf32 mma)
#pragma unroll
        for (int kk = 0; kk < 8; kk++) {
            unsigned af[2][4];
#pragma unroll
            for (int mi = 0; mi < 2; mi++) {
                const unsigned* b = &Ps[(wm * 32 + mi * 16 + fr) * ASTRIDE + kk * 8 + fc];
                af[mi][0] = b[0];
                af[mi][1] = b[8 * ASTRIDE];
                af[mi][2] = b[4];
                af[mi][3] = b[8 * ASTRIDE + 4];
            }
            unsigned bf[4][2];
#pragma unroll
            for (int ni = 0; ni < 4; ni++) {
                const unsigned* b = &Vt[(wn * 32 + ni * 8 + fr) * ASTRIDE + kk * 8 + fc];
                bf[ni][0] = b[0];
                bf[ni][1] = b[4];
            }
#pragma unroll
            for (int mi = 0; mi < 2; mi++)
#pragma unroll
                for (int ni = 0; ni < 4; ni++)
                    MMA_TF32(O[mi][ni], af[mi], bf[ni]);
        }
    }

    // Epilogue: normalize, store to [B*T, C]
    const int b = bh >> 4;
    const int h = bh & 15;
#pragma unroll
    for (int mi = 0; mi < 2; mi++)
#pragma unroll
    for (int hh = 0; hh < 2; hh++) {
        int slot = mi * 2 + hh;
        float linv = 1.0f / l_i[slot];
        int row = q0 + wm * 32 + mi * 16 + fr + hh * 8;
        float* op = g_att + ((size_t)(b * TT) + row) * DIMC + h * HDIM + wn * 32;
#pragma unroll
        for (int ni = 0; ni < 4; ni++) {
            *(float2*)(op + ni * 8 + fc * 2) =
                make_float2(O[mi][ni][hh * 2 + 0] * linv,
                            O[mi][ni][hh * 2 + 1] * linv);
        }
    }
}

#define ATTN_SMEM_BYTES ((128*ASTRIDE + 64*ASTRIDE + 64*ASTRIDE + 128*ASTRIDE) * 4 + 2 * 2 * 128 * 4)

// ---------------------------------------------------------------------------
extern "C" void kernel_launch(void* const* d_in, const int* in_sizes, int n_in,
                              void* d_out, int out_size)
{
    const float* x  = (const float*)d_in[0];
    // d_in[1] = mask (unused; causal applied analytically)
    const float* wq = (const float*)d_in[2];
    const float* wk = (const float*)d_in[3];
    const float* wv = (const float*)d_in[4];
    const float* wo = (const float*)d_in[5];
    float* out = (float*)d_out;

    float *dq, *dk, *dv, *datt;
    cudaGetSymbolAddress((void**)&dq,   g_q);
    cudaGetSymbolAddress((void**)&dk,   g_k);
    cudaGetSymbolAddress((void**)&dv,   g_v);
    cudaGetSymbolAddress((void**)&datt, g_att);

    cudaFuncSetAttribute(attn_kernel,
                         cudaFuncAttributeMaxDynamicSharedMemorySize,
                         ATTN_SMEM_BYTES);

    // QKV projections: 128x128 tiles, grid (8, 64, 3), 128 threads
    gemm_kernel<<<dim3(8, 64, 3), 128>>>(x, wq, wk, wv, dq, dk, dv, 1);

    // Flash attention: grid (16 q-tiles, 64 b*h)
    attn_kernel<<<dim3(16, 64), 256, ATTN_SMEM_BYTES>>>();

    // Output projection
    gemm_kernel<<<dim3(8, 64, 1), 128>>>(datt, wo, wo, wo, out, out, out, 0);
}

// round 7
// speedup vs baseline: 1.2588x; 1.2588x over previous
#include <cuda_runtime.h>
#include <cuda_bf16.h>

#define DIMC 1024
#define NHEAD 16
#define HDIM 64
#define BB 4
#define TT 2048
#define MROWS (BB * TT)   // 8192

// Scratch (device globals — allocation-free contract)
__device__ float g_q[BB * NHEAD * TT * HDIM];   // [B,H,T,D]
__device__ float g_k[BB * NHEAD * TT * HDIM];
__device__ float g_v[BB * NHEAD * TT * HDIM];
__device__ float g_att[MROWS * DIMC];           // [B*T, C] attention output

__device__ __forceinline__ unsigned f2tf32(float x) {
    unsigned u;
    asm("cvt.rna.tf32.f32 %0, %1;" : "=r"(u) : "f"(x));
    return u;
}

// 2^x on the FMA/ALU pipes (no MUFU). x <= 0 expected; clamped at -120.
__device__ __forceinline__ float exp2_fast(float x) {
    x = fmaxf(x, -120.f);
    float n = floorf(x);
    float f = x - n;                 // [0,1)
    float p = 1.78656e-4f;           // ~(ln2)^6/720
    p = fmaf(p, f, 1.33336e-3f);
    p = fmaf(p, f, 9.61813e-3f);
    p = fmaf(p, f, 5.55041e-2f);
    p = fmaf(p, f, 2.40226507e-1f);
    p = fmaf(p, f, 6.93147181e-1f);
    p = fmaf(p, f, 1.0f);
    return __uint_as_float(__float_as_uint(p) + (((int)n) << 23));
}

#define MMA_TF32(d, a, b)                                                    \
    asm volatile("mma.sync.aligned.m16n8k8.row.col.f32.tf32.tf32.f32 "        \
                 "{%0,%1,%2,%3}, {%4,%5,%6,%7}, {%8,%9}, {%0,%1,%2,%3};"      \
                 : "+f"(d[0]), "+f"(d[1]), "+f"(d[2]), "+f"(d[3])             \
                 : "r"(a[0]), "r"(a[1]), "r"(a[2]), "r"(a[3]),                \
                   "r"(b[0]), "r"(b[1]))

// ---------------------------------------------------------------------------
// TF32 tensor-core GEMM (R5 config — known good): 128x128 block, BK=8,
// 256 threads (8 warps in 2x4 grid, 64x32/warp), double-buffered.
// ---------------------------------------------------------------------------
#define KSTRIDE 136

__global__ __launch_bounds__(256, 2) void gemm_kernel(
    const float* __restrict__ A,
    const float* __restrict__ W0, const float* __restrict__ W1,
    const float* __restrict__ W2,
    float* __restrict__ D0, float* __restrict__ D1, float* __restrict__ D2,
    int qkv_mode)
{
    __shared__ unsigned As[2][8][KSTRIDE];
    __shared__ unsigned Bs[2][8][KSTRIDE];

    const float* W = W0;
    float* D = D0;
    if (blockIdx.z == 1) { W = W1; D = D1; }
    else if (blockIdx.z == 2) { W = W2; D = D2; }

    const int tid  = threadIdx.x;
    const int lane = tid & 31;
    const int w    = tid >> 5;
    const int wm   = w >> 2;
    const int wn   = w & 3;
    const int r0 = blockIdx.y * 128;
    const int c0 = blockIdx.x * 128;

    const int lrow = tid >> 1;
    const int lk   = (tid & 1) * 4;
    const float* Ap = A + (size_t)(r0 + lrow) * DIMC + lk;
    const float* Wp = W + (size_t)(c0 + lrow) * DIMC + lk;

    const int fr = lane >> 2;
    const int fc = lane & 3;

    float acc[4][4][4];
#pragma unroll
    for (int mi = 0; mi < 4; mi++)
#pragma unroll
        for (int ni = 0; ni < 4; ni++)
#pragma unroll
            for (int e = 0; e < 4; e++) acc[mi][ni][e] = 0.f;

    {
        float4 a4 = *(const float4*)(Ap);
        float4 b4 = *(const float4*)(Wp);
        As[0][lk + 0][lrow] = f2tf32(a4.x); As[0][lk + 1][lrow] = f2tf32(a4.y);
        As[0][lk + 2][lrow] = f2tf32(a4.z); As[0][lk + 3][lrow] = f2tf32(a4.w);
        Bs[0][lk + 0][lrow] = f2tf32(b4.x); Bs[0][lk + 1][lrow] = f2tf32(b4.y);
        Bs[0][lk + 2][lrow] = f2tf32(b4.z); Bs[0][lk + 3][lrow] = f2tf32(b4.w);
    }
    __syncthreads();

    int buf = 0;
    for (int kt = 1; kt <= DIMC / 8; kt++) {
        float4 na, nb;
        const bool more = (kt < DIMC / 8);
        if (more) {
            na = *(const float4*)(Ap + kt * 8);
            nb = *(const float4*)(Wp + kt * 8);
        }

        unsigned af[4][4], bfr[4][2];
#pragma unroll
        for (int mi = 0; mi < 4; mi++) {
            int r = wm * 64 + mi * 16 + fr;
            af[mi][0] = As[buf][fc][r];
            af[mi][1] = As[buf][fc][r + 8];
            af[mi][2] = As[buf][fc + 4][r];
            af[mi][3] = As[buf][fc + 4][r + 8];
        }
#pragma unroll
        for (int ni = 0; ni < 4; ni++) {
            int n = wn * 32 + ni * 8 + fr;
            bfr[ni][0] = Bs[buf][fc][n];
            bfr[ni][1] = Bs[buf][fc + 4][n];
        }
#pragma unroll
        for (int mi = 0; mi < 4; mi++)
#pragma unroll
            for (int ni = 0; ni < 4; ni++)
                MMA_TF32(acc[mi][ni], af[mi], bfr[ni]);

        if (more) {
            int nb_ = buf ^ 1;
            As[nb_][lk + 0][lrow] = f2tf32(na.x); As[nb_][lk + 1][lrow] = f2tf32(na.y);
            As[nb_][lk + 2][lrow] = f2tf32(na.z); As[nb_][lk + 3][lrow] = f2tf32(na.w);
            Bs[nb_][lk + 0][lrow] = f2tf32(nb.x); Bs[nb_][lk + 1][lrow] = f2tf32(nb.y);
            Bs[nb_][lk + 2][lrow] = f2tf32(nb.z); Bs[nb_][lk + 3][lrow] = f2tf32(nb.w);
            __syncthreads();
            buf ^= 1;
        }
    }

    if (!qkv_mode) {
#pragma unroll
        for (int mi = 0; mi < 4; mi++) {
            int r = r0 + wm * 64 + mi * 16 + fr;
#pragma unroll
            for (int ni = 0; ni < 4; ni++) {
                int c = c0 + wn * 32 + ni * 8 + fc * 2;
                *(float2*)(D + (size_t)r * DIMC + c) =
                    make_float2(acc[mi][ni][0], acc[mi][ni][1]);
                *(float2*)(D + (size_t)(r + 8) * DIMC + c) =
                    make_float2(acc[mi][ni][2], acc[mi][ni][3]);
            }
        }
    } else {
#pragma unroll
        for (int mi = 0; mi < 4; mi++) {
            int row = r0 + wm * 64 + mi * 16 + fr;
#pragma unroll
            for (int half = 0; half < 2; half++) {
                int rr = row + half * 8;
                int b = rr >> 11;
                int t = rr & 2047;
#pragma unroll
                for (int ni = 0; ni < 4; ni++) {
                    int cc = wn * 32 + ni * 8 + fc * 2;
                    int h = blockIdx.x * 2 + (cc >> 6);
                    int d = cc & 63;
                    size_t idx = (((size_t)(b * NHEAD + h) * TT + t) * HDIM) + d;
                    *(float2*)(D + idx) =
                        make_float2(acc[mi][ni][half * 2 + 0],
                                    acc[mi][ni][half * 2 + 1]);
                }
            }
        }
    }
}

// ---------------------------------------------------------------------------
// Flash attention, tensor-core, full-row warps. BQ=128, BK=64, 256 threads =
// 8 warps stacked on M; each warp owns 16 rows x all 64 cols (1 m-atom x
// 8 n-atoms). Row softmax is warp-local (registers + 2 shuffles); the P tile
// is warp-private in smem, so PV needs only __syncwarp(). 2 CTA syncs/tile.
// ---------------------------------------------------------------------------
#define ASTRIDE 68

__global__ __launch_bounds__(256) void attn_kernel()
{
    extern __shared__ unsigned smu[];
    unsigned* Qs = smu;                    // [128][68] tf32, scaled by 0.125*log2e
    unsigned* Ks = Qs + 128 * ASTRIDE;     // [64][68]  tf32, [key][d]
    unsigned* Vt = Ks + 64 * ASTRIDE;      // [64][68]  tf32, [d][key]
    unsigned* Ps = Vt + 64 * ASTRIDE;      // [128][68] tf32 probs (warp-private rows)

    const int tid  = threadIdx.x;
    const int lane = tid & 31;
    const int w    = tid >> 5;        // warp owns rows w*16 .. w*16+15
    const int fr   = lane >> 2;       // 0..7
    const int fc   = lane & 3;        // 0..3

    const int bh = blockIdx.y;
    const int q0 = (gridDim.x - 1 - blockIdx.x) * 128;   // heavy tiles first

    const float* Q = g_q + (size_t)bh * TT * HDIM;
    const float* K = g_k + (size_t)bh * TT * HDIM;
    const float* V = g_v + (size_t)bh * TT * HDIM;

    const float qsc = 0.125f * 1.4426950408889634f;  // scale * log2(e)

    // Stage Q (tf32, scaled): 128 x 64
#pragma unroll
    for (int it = 0; it < 8; it++) {
        int e = tid + it * 256;
        int r = e >> 4, dq = (e & 15) * 4;
        float4 v4 = *(const float4*)(Q + (size_t)(q0 + r) * HDIM + dq);
        unsigned* p = &Qs[r * ASTRIDE + dq];
        p[0] = f2tf32(v4.x * qsc); p[1] = f2tf32(v4.y * qsc);
        p[2] = f2tf32(v4.z * qsc); p[3] = f2tf32(v4.w * qsc);
    }

    // O accumulators: 16 rows x 64 cols per warp -> 8 n-atoms
    float O[8][4];
#pragma unroll
    for (int ni = 0; ni < 8; ni++)
#pragma unroll
        for (int e = 0; e < 4; e++) O[ni][e] = 0.f;
    float m_i[2] = {-1e30f, -1e30f};   // rows w*16+fr, +8
    float l_i[2] = {0.f, 0.f};

    const int rbase = w * 16 + fr;
    const int ntiles = (q0 >> 6) + 2;

    for (int kt = 0; kt < ntiles; kt++) {
        const int k0 = kt * 64;
        __syncthreads();   // prev tile's PV reads of Ks/Vt done

        // Stage K: Ks[key][d]
#pragma unroll
        for (int it = 0; it < 4; it++) {
            int e = tid + it * 256;
            int k = e >> 4, dq = (e & 15) * 4;
            float4 kv = *(const float4*)(K + (size_t)(k0 + k) * HDIM + dq);
            unsigned* p = &Ks[k * ASTRIDE + dq];
            p[0] = f2tf32(kv.x); p[1] = f2tf32(kv.y);
            p[2] = f2tf32(kv.z); p[3] = f2tf32(kv.w);
        }
        // Stage V transposed: Vt[d][key]
#pragma unroll
        for (int it = 0; it < 4; it++) {
            int e = tid + it * 256;
            int d = e & 63;
            int kq = (e >> 6) * 4;
            float v0 = V[(size_t)(k0 + kq + 0) * HDIM + d];
            float v1 = V[(size_t)(k0 + kq + 1) * HDIM + d];
            float v2 = V[(size_t)(k0 + kq + 2) * HDIM + d];
            float v3 = V[(size_t)(k0 + kq + 3) * HDIM + d];
            *(uint4*)&Vt[d * ASTRIDE + kq] =
                make_uint4(f2tf32(v0), f2tf32(v1), f2tf32(v2), f2tf32(v3));
        }
        __syncthreads();

        // S = Qs @ Ks^T : warp computes 16 rows x 64 cols
        float sacc[8][4];
#pragma unroll
        for (int ni = 0; ni < 8; ni++)
#pragma unroll
            for (int e = 0; e < 4; e++) sacc[ni][e] = 0.f;

#pragma unroll
        for (int kk = 0; kk < 8; kk++) {
            unsigned af[4];
            {
                const unsigned* b = &Qs[rbase * ASTRIDE + kk * 8 + fc];
                af[0] = b[0];
                af[1] = b[8 * ASTRIDE];
                af[2] = b[4];
                af[3] = b[8 * ASTRIDE + 4];
            }
#pragma unroll
            for (int ni = 0; ni < 8; ni++) {
                const unsigned* b = &Ks[(ni * 8 + fr) * ASTRIDE + kk * 8 + fc];
                unsigned bf[2] = {b[0], b[4]};
                MMA_TF32(sacc[ni], af, bf);
            }
        }

        // Warp-local softmax (log2 domain). Row h=0: rbase; h=1: rbase+8.
        const bool need_mask = (k0 + 63 > q0);
        float alpha[2];
#pragma unroll
        for (int h = 0; h < 2; h++) {
            const int rg = q0 + rbase + h * 8;
            float rm = -1e30f;
#pragma unroll
            for (int ni = 0; ni < 8; ni++)
#pragma unroll
            for (int e = 0; e < 2; e++) {
                float s = sacc[ni][h * 2 + e];
                if (need_mask && (k0 + ni * 8 + fc * 2 + e > rg)) s = -1e30f;
                sacc[ni][h * 2 + e] = s;
                rm = fmaxf(rm, s);
            }
            rm = fmaxf(rm, __shfl_xor_sync(0xffffffffu, rm, 1));
            rm = fmaxf(rm, __shfl_xor_sync(0xffffffffu, rm, 2));
            float mnew = fmaxf(m_i[h], rm);
            float al = exp2_fast(m_i[h] - mnew);
            m_i[h] = mnew;
            alpha[h] = al;
            float rs = 0.f;
#pragma unroll
            for (int ni = 0; ni < 8; ni++) {
                float p0 = exp2_fast(sacc[ni][h * 2 + 0] - mnew);
                float p1 = exp2_fast(sacc[ni][h * 2 + 1] - mnew);
                rs += p0 + p1;
                *(uint2*)&Ps[(rbase + h * 8) * ASTRIDE + ni * 8 + fc * 2] =
                    make_uint2(f2tf32(p0), f2tf32(p1));
            }
            rs += __shfl_xor_sync(0xffffffffu, rs, 1);
            rs += __shfl_xor_sync(0xffffffffu, rs, 2);
            l_i[h] = l_i[h] * al + rs;
#pragma unroll
            for (int ni = 0; ni < 8; ni++) {
                O[ni][h * 2 + 0] *= al;
                O[ni][h * 2 + 1] *= al;
            }
        }
        __syncwarp();   // P rows are warp-private; warp-level visibility only

        // O += P @ V
#pragma unroll
        for (int kk = 0; kk < 8; kk++) {
            unsigned af[4];
            {
                const unsigned* b = &Ps[rbase * ASTRIDE + kk * 8 + fc];
                af[0] = b[0];
                af[1] = b[8 * ASTRIDE];
                af[2] = b[4];
                af[3] = b[8 * ASTRIDE + 4];
            }
#pragma unroll
            for (int ni = 0; ni < 8; ni++) {
                const unsigned* b = &Vt[(ni * 8 + fr) * ASTRIDE + kk * 8 + fc];
                unsigned bf[2] = {b[0], b[4]};
                MMA_TF32(O[ni], af, bf);
            }
        }
    }

    // Epilogue: normalize, store to [B*T, C]
    const int b = bh >> 4;
    const int h = bh & 15;
#pragma unroll
    for (int hh = 0; hh < 2; hh++) {
        float linv = 1.0f / l_i[hh];
        int row = q0 + rbase + hh * 8;
        float* op = g_att + ((size_t)(b * TT) + row) * DIMC + h * HDIM;
#pragma unroll
        for (int ni = 0; ni < 8; ni++) {
            *(float2*)(op + ni * 8 + fc * 2) =
                make_float2(O[ni][hh * 2 + 0] * linv,
                            O[ni][hh * 2 + 1] * linv);
        }
    }
}

#define ATTN_SMEM_BYTES ((128*ASTRIDE + 64*ASTRIDE + 64*ASTRIDE + 128*ASTRIDE) * 4)

// ---------------------------------------------------------------------------
extern "C" void kernel_launch(void* const* d_in, const int* in_sizes, int n_in,
                              void* d_out, int out_size)
{
    const float* x  = (const float*)d_in[0];
    // d_in[1] = mask (unused; causal applied analytically)
    const float* wq = (const float*)d_in[2];
    const float* wk = (const float*)d_in[3];
    const float* wv = (const float*)d_in[4];
    const float* wo = (const float*)d_in[5];
    float* out = (float*)d_out;

    float *dq, *dk, *dv, *datt;
    cudaGetSymbolAddress((void**)&dq,   g_q);
    cudaGetSymbolAddress((void**)&dk,   g_k);
    cudaGetSymbolAddress((void**)&dv,   g_v);
    cudaGetSymbolAddress((void**)&datt, g_att);

    cudaFuncSetAttribute(attn_kernel,
                         cudaFuncAttributeMaxDynamicSharedMemorySize,
                         ATTN_SMEM_BYTES);

    // QKV projections: 128x128 tiles, grid (8, 64, 3), 256 threads
    gemm_kernel<<<dim3(8, 64, 3), 256>>>(x, wq, wk, wv, dq, dk, dv, 1);

    // Flash attention: grid (16 q-tiles, 64 b*h)
    attn_kernel<<<dim3(16, 64), 256, ATTN_SMEM_BYTES>>>();

    // Output projection
    gemm_kernel<<<dim3(8, 64, 1), 256>>>(datt, wo, wo, wo, out, out, out, 0);
}